// round 2
// baseline (speedup 1.0000x reference)
#include <cuda_runtime.h>

#define FDIM 256
#define HEADS 4
#define HEAD_DIM 64
#define NEG_SLOPE 0.2f
#define MAX_N 50000
#define MAX_E 800000

// Scratch (static __device__ — allocation-free per harness rules)
__device__ __align__(16) float g_h[MAX_N * FDIM];        // 51.2 MB, h = xW
__device__ __align__(16) float g_asrc[MAX_N * HEADS];
__device__ __align__(16) float g_adst[MAX_N * HEADS];
__device__ __align__(16) float g_maxv[MAX_N * HEADS];
__device__ __align__(16) float g_denom[MAX_N * HEADS];
__device__ int g_is64;

__device__ __forceinline__ void atomicMaxFloat(float* addr, float v) {
    if (v >= 0.0f) atomicMax((int*)addr, __float_as_int(v));
    else           atomicMin((unsigned int*)addr, __float_as_uint(v));
}

__device__ __forceinline__ void red_add_v4(float* addr, float a, float b, float c, float d) {
    asm volatile("red.global.add.v4.f32 [%0], {%1,%2,%3,%4};"
                 :: "l"(addr), "f"(a), "f"(b), "f"(c), "f"(d) : "memory");
}

__device__ __forceinline__ float lrelu(float v) {
    return v > 0.0f ? v : NEG_SLOPE * v;
}

// Load edge index at position pos, dtype-agnostic (int32 vs int64), clamped.
__device__ __forceinline__ int load_idx(const void* ei, long long pos, int is64, int N) {
    int v;
    if (is64) v = (int)((const long long*)ei)[pos];
    else      v = ((const int*)ei)[pos];
    v = v < 0 ? 0 : (v >= N ? N - 1 : v);
    return v;
}

// ---------------------------------------------------------------------------
// Detect int64 vs int32 edge buffer: int64 values < 2^31 have zero odd words.
// ---------------------------------------------------------------------------
__global__ void detect_kernel(const unsigned int* __restrict__ w, int nwords) {
    int is64 = 1;
    int lim = nwords < 256 ? nwords : 256;
    for (int i = 1; i < lim; i += 2)
        if (w[i] != 0u) { is64 = 0; break; }
    g_is64 = is64;
}

// ---------------------------------------------------------------------------
// init: out = bias broadcast; maxv = -inf; denom = 0
// ---------------------------------------------------------------------------
__global__ void init_kernel(float* __restrict__ out, const float* __restrict__ bias, int N) {
    int i = blockIdx.x * blockDim.x + threadIdx.x;
    int total = N * FDIM;
    if (i < total) out[i] = bias[i & (FDIM - 1)];
    if (i < N * HEADS) {
        ((int*)g_maxv)[i] = 0xFF800000;  // -inf bits
        g_denom[i] = 0.0f;
    }
}

// ---------------------------------------------------------------------------
// GEMM: g_h[M,256] = x[M,256] @ W[256,256]. BM=BN=64, BK=32, 16x16 threads, 4x4 tile.
// ---------------------------------------------------------------------------
__global__ void gemm_kernel(const float* __restrict__ x, const float* __restrict__ W, int M) {
    __shared__ float As[32][65];  // [k][m], pad 65 -> conflict-free stores
    __shared__ float Bs[32][64];  // [k][n]
    int tid = threadIdx.x;
    int tx = tid & 15, ty = tid >> 4;
    int row0 = blockIdx.x * 64;
    int col0 = blockIdx.y * 64;
    float acc[4][4];
#pragma unroll
    for (int i = 0; i < 4; i++)
#pragma unroll
        for (int j = 0; j < 4; j++) acc[i][j] = 0.0f;

    for (int k0 = 0; k0 < FDIM; k0 += 32) {
#pragma unroll
        for (int it = 0; it < 2; it++) {
            int i = tid + it * 256;          // 0..511
            int m = i >> 3;                  // 0..63
            int kk = (i & 7) * 4;            // 0..28
            float4 v = make_float4(0.f, 0.f, 0.f, 0.f);
            int r = row0 + m;
            if (r < M) v = *(const float4*)&x[(size_t)r * FDIM + k0 + kk];
            As[kk + 0][m] = v.x; As[kk + 1][m] = v.y;
            As[kk + 2][m] = v.z; As[kk + 3][m] = v.w;
        }
#pragma unroll
        for (int it = 0; it < 2; it++) {
            int i = tid + it * 256;
            int kk = i >> 4;                 // 0..31
            int n = (i & 15) * 4;            // 0..60
            *(float4*)&Bs[kk][n] = *(const float4*)&W[(size_t)(k0 + kk) * FDIM + col0 + n];
        }
        __syncthreads();
#pragma unroll
        for (int kk = 0; kk < 32; kk++) {
            float a[4], b[4];
#pragma unroll
            for (int i = 0; i < 4; i++) a[i] = As[kk][ty * 4 + i];
#pragma unroll
            for (int j = 0; j < 4; j++) b[j] = Bs[kk][tx * 4 + j];
#pragma unroll
            for (int i = 0; i < 4; i++)
#pragma unroll
                for (int j = 0; j < 4; j++) acc[i][j] = fmaf(a[i], b[j], acc[i][j]);
        }
        __syncthreads();
    }
#pragma unroll
    for (int i = 0; i < 4; i++) {
        int r = row0 + ty * 4 + i;
        if (r < M)
            *(float4*)&g_h[(size_t)r * FDIM + col0 + tx * 4] =
                make_float4(acc[i][0], acc[i][1], acc[i][2], acc[i][3]);
    }
}

// ---------------------------------------------------------------------------
// Per-node attention dots: one warp per node. Lane l handles floats [8l, 8l+8).
// head = l/8; segmented 8-lane reduce.
// ---------------------------------------------------------------------------
__global__ void adot_kernel(const float* __restrict__ att_src,
                            const float* __restrict__ att_dst, int N) {
    int gw = (blockIdx.x * blockDim.x + threadIdx.x) >> 5;
    int lane = threadIdx.x & 31;
    if (gw >= N) return;
    const float4* hp = (const float4*)(g_h + (size_t)gw * FDIM);
    float4 v0 = hp[lane * 2], v1 = hp[lane * 2 + 1];
    int head = lane >> 3;
    int off = head * HEAD_DIM + (lane & 7) * 8;
    const float4* sp = (const float4*)(att_src + off);
    const float4* dp = (const float4*)(att_dst + off);
    float4 s0 = sp[0], s1 = sp[1];
    float4 d0 = dp[0], d1 = dp[1];
    float ps = v0.x*s0.x + v0.y*s0.y + v0.z*s0.z + v0.w*s0.w
             + v1.x*s1.x + v1.y*s1.y + v1.z*s1.z + v1.w*s1.w;
    float pd = v0.x*d0.x + v0.y*d0.y + v0.z*d0.z + v0.w*d0.w
             + v1.x*d1.x + v1.y*d1.y + v1.z*d1.z + v1.w*d1.w;
#pragma unroll
    for (int sh = 1; sh < 8; sh <<= 1) {
        ps += __shfl_xor_sync(0xFFFFFFFF, ps, sh);
        pd += __shfl_xor_sync(0xFFFFFFFF, pd, sh);
    }
    if ((lane & 7) == 0) {
        g_asrc[gw * HEADS + head] = ps;
        g_adst[gw * HEADS + head] = pd;
    }
}

// ---------------------------------------------------------------------------
// Pass A: per-edge leaky_relu(a_src[s]+a_dst[d]) -> atomic segment max on dst
// ---------------------------------------------------------------------------
__global__ void edge_max_kernel(const void* __restrict__ ei, int E, int N) {
    int e = blockIdx.x * blockDim.x + threadIdx.x;
    int ET = E + N;
    if (e >= ET) return;
    int is64 = g_is64;
    int s, d;
    if (e < E) {
        s = load_idx(ei, e, is64, N);
        d = load_idx(ei, (long long)E + e, is64, N);
    } else s = d = e - E;
    float4 as = *(const float4*)&g_asrc[s * 4];
    float4 ad = *(const float4*)&g_adst[d * 4];
    atomicMaxFloat(&g_maxv[d * 4 + 0], lrelu(as.x + ad.x));
    atomicMaxFloat(&g_maxv[d * 4 + 1], lrelu(as.y + ad.y));
    atomicMaxFloat(&g_maxv[d * 4 + 2], lrelu(as.z + ad.z));
    atomicMaxFloat(&g_maxv[d * 4 + 3], lrelu(as.w + ad.w));
}

// ---------------------------------------------------------------------------
// Pass B: per-edge exp(v - max[dst]) -> atomic segment sum on dst
// ---------------------------------------------------------------------------
__global__ void edge_sum_kernel(const void* __restrict__ ei, int E, int N) {
    int e = blockIdx.x * blockDim.x + threadIdx.x;
    int ET = E + N;
    if (e >= ET) return;
    int is64 = g_is64;
    int s, d;
    if (e < E) {
        s = load_idx(ei, e, is64, N);
        d = load_idx(ei, (long long)E + e, is64, N);
    } else s = d = e - E;
    float4 as = *(const float4*)&g_asrc[s * 4];
    float4 ad = *(const float4*)&g_adst[d * 4];
    float4 mx = *(const float4*)&g_maxv[d * 4];
    atomicAdd(&g_denom[d * 4 + 0], __expf(lrelu(as.x + ad.x) - mx.x));
    atomicAdd(&g_denom[d * 4 + 1], __expf(lrelu(as.y + ad.y) - mx.y));
    atomicAdd(&g_denom[d * 4 + 2], __expf(lrelu(as.z + ad.z) - mx.z));
    atomicAdd(&g_denom[d * 4 + 3], __expf(lrelu(as.w + ad.w) - mx.w));
}

// ---------------------------------------------------------------------------
// Pass C: warp per edge. Recompute alpha, scatter alpha*h[src] -> out[dst]
// via red.global.add.v4.f32 (16B vector reductions, L2-resident RMW).
// ---------------------------------------------------------------------------
__global__ void edge_scatter_kernel(const void* __restrict__ ei,
                                    float* __restrict__ out, int E, int N) {
    int gw = (blockIdx.x * blockDim.x + threadIdx.x) >> 5;
    int lane = threadIdx.x & 31;
    int ET = E + N;
    if (gw >= ET) return;
    int is64 = g_is64;
    int s, d;
    if (gw < E) {
        s = load_idx(ei, gw, is64, N);
        d = load_idx(ei, (long long)E + gw, is64, N);
    } else s = d = gw - E;
    float4 as = *(const float4*)&g_asrc[s * 4];
    float4 ad = *(const float4*)&g_adst[d * 4];
    float4 mx = *(const float4*)&g_maxv[d * 4];
    float4 dn = *(const float4*)&g_denom[d * 4];
    float al0 = __expf(lrelu(as.x + ad.x) - mx.x) / dn.x;
    float al1 = __expf(lrelu(as.y + ad.y) - mx.y) / dn.y;
    float al2 = __expf(lrelu(as.z + ad.z) - mx.z) / dn.z;
    float al3 = __expf(lrelu(as.w + ad.w) - mx.w) / dn.w;

    const float4* hp = (const float4*)(g_h + (size_t)s * FDIM);
    float* op = out + (size_t)d * FDIM;

    // float4 index i covers head = i/16. i=lane -> heads 0/1; i=lane+32 -> heads 2/3.
    float aA = (lane < 16) ? al0 : al1;
    float aB = (lane < 16) ? al2 : al3;

    float4 h0 = hp[lane];
    red_add_v4(op + lane * 4, aA * h0.x, aA * h0.y, aA * h0.z, aA * h0.w);
    float4 h1 = hp[lane + 32];
    red_add_v4(op + (lane + 32) * 4, aB * h1.x, aB * h1.y, aB * h1.z, aB * h1.w);
}

// ---------------------------------------------------------------------------
extern "C" void kernel_launch(void* const* d_in, const int* in_sizes, int n_in,
                              void* d_out, int out_size) {
    const float* x        = (const float*)d_in[0];
    const void*  ei       = d_in[1];
    const float* W        = (const float*)d_in[2];
    const float* att_src  = (const float*)d_in[3];
    const float* att_dst  = (const float*)d_in[4];
    const float* bias     = (const float*)d_in[5];
    float* out = (float*)d_out;

    int N = in_sizes[0] / FDIM;
    int E = in_sizes[1] / 2;
    int ET = E + N;

    detect_kernel<<<1, 1>>>((const unsigned int*)ei, in_sizes[1]);

    int total = N * FDIM;
    init_kernel<<<(total + 255) / 256, 256>>>(out, bias, N);

    dim3 ggrid((N + 63) / 64, FDIM / 64);
    gemm_kernel<<<ggrid, 256>>>(x, W, N);

    adot_kernel<<<(N * 32 + 255) / 256, 256>>>(att_src, att_dst, N);

    edge_max_kernel<<<(ET + 255) / 256, 256>>>(ei, E, N);
    edge_sum_kernel<<<(ET + 255) / 256, 256>>>(ei, E, N);
    edge_scatter_kernel<<<((size_t)ET * 32 + 255) / 256, 256>>>(ei, out, E, N);
}

// round 3
// speedup vs baseline: 1.2920x; 1.2920x over previous
#include <cuda_runtime.h>

#define FDIM 256
#define HEADS 4
#define HEAD_DIM 64
#define NEG_SLOPE 0.2f
#define MAX_N 50000
#define MAX_E 800000
#define SCAN_T 1024

// Scratch (static __device__ — allocation-free per harness rules)
__device__ __align__(16) float g_h[MAX_N * FDIM];        // 51.2 MB, h = xW
__device__ __align__(16) float g_asrc[MAX_N * HEADS];
__device__ __align__(16) float g_adst[MAX_N * HEADS];
__device__ int g_count[MAX_N];
__device__ int g_rowstart[MAX_N + 1];
__device__ int g_cursor[MAX_N];
__device__ int g_esrc[MAX_E + MAX_N];
__device__ int g_is64;

__device__ __forceinline__ float lrelu(float v) {
    return v > 0.0f ? v : NEG_SLOPE * v;
}

// Load edge index at position pos, dtype-agnostic (int32 vs int64), clamped.
__device__ __forceinline__ int load_idx(const void* ei, long long pos, int is64, int N) {
    int v;
    if (is64) v = (int)((const long long*)ei)[pos];
    else      v = ((const int*)ei)[pos];
    v = v < 0 ? 0 : (v >= N ? N - 1 : v);
    return v;
}

// ---------------------------------------------------------------------------
// Detect int64 vs int32 edge buffer: int64 values < 2^31 have zero odd words.
// ---------------------------------------------------------------------------
__global__ void detect_kernel(const unsigned int* __restrict__ w, int nwords) {
    int is64 = 1;
    int lim = nwords < 256 ? nwords : 256;
    for (int i = 1; i < lim; i += 2)
        if (w[i] != 0u) { is64 = 0; break; }
    g_is64 = is64;
}

__global__ void zero_kernel(int N) {
    int i = blockIdx.x * blockDim.x + threadIdx.x;
    if (i < N) g_count[i] = 0;
}

// ---------------------------------------------------------------------------
// Histogram of destination degrees (incl. self loops)
// ---------------------------------------------------------------------------
__global__ void hist_kernel(const void* __restrict__ ei, int E, int N) {
    int e = blockIdx.x * blockDim.x + threadIdx.x;
    int ET = E + N;
    if (e >= ET) return;
    int d = (e < E) ? load_idx(ei, (long long)E + e, g_is64, N) : e - E;
    atomicAdd(&g_count[d], 1);
}

// ---------------------------------------------------------------------------
// Single-block exclusive scan of g_count -> g_rowstart / g_cursor
// ---------------------------------------------------------------------------
__global__ void scan_kernel(int N) {
    __shared__ int sh[SCAN_T];
    int t = threadIdx.x;
    int chunk = (N + SCAN_T - 1) / SCAN_T;
    int base = t * chunk;
    int s = 0;
    for (int j = 0; j < chunk; j++) {
        int i = base + j;
        if (i < N) s += g_count[i];
    }
    sh[t] = s;
    __syncthreads();
    for (int off = 1; off < SCAN_T; off <<= 1) {
        int v = (t >= off) ? sh[t - off] : 0;
        __syncthreads();
        sh[t] += v;
        __syncthreads();
    }
    int run = sh[t] - s;  // exclusive prefix
    for (int j = 0; j < chunk; j++) {
        int i = base + j;
        if (i < N) {
            g_rowstart[i] = run;
            g_cursor[i] = run;
            run += g_count[i];
        }
    }
    if (t == SCAN_T - 1) g_rowstart[N] = sh[SCAN_T - 1];
}

// ---------------------------------------------------------------------------
// Fill CSR: scatter src indices into dst-grouped buckets
// ---------------------------------------------------------------------------
__global__ void fill_kernel(const void* __restrict__ ei, int E, int N) {
    int e = blockIdx.x * blockDim.x + threadIdx.x;
    int ET = E + N;
    if (e >= ET) return;
    int is64 = g_is64;
    int s, d;
    if (e < E) {
        s = load_idx(ei, e, is64, N);
        d = load_idx(ei, (long long)E + e, is64, N);
    } else s = d = e - E;
    int pos = atomicAdd(&g_cursor[d], 1);
    g_esrc[pos] = s;
}

// ---------------------------------------------------------------------------
// GEMM: g_h[M,256] = x[M,256] @ W[256,256]. BM=128, BN=64, BK=16,
// 256 threads, 8x4 accumulators per thread.
// ---------------------------------------------------------------------------
__global__ void gemm_kernel(const float* __restrict__ x, const float* __restrict__ W, int M) {
    __shared__ float As[16][132];  // [k][m], padded
    __shared__ float Bs[16][64];   // [k][n]
    int tid = threadIdx.x;
    int tx = tid & 15, ty = tid >> 4;
    int row0 = blockIdx.x * 128;
    int col0 = blockIdx.y * 64;

    float acc[8][4];
#pragma unroll
    for (int i = 0; i < 8; i++)
#pragma unroll
        for (int j = 0; j < 4; j++) acc[i][j] = 0.0f;

    // A load mapping: thread i -> row r = i>>1, k-quad kq = (i&1)*8
    int ar = tid >> 1;
    int akq = (tid & 1) * 8;
    // B load mapping: thread i -> k row = i>>4, col = (i&15)*4
    int bk = tid >> 4;
    int bn = (tid & 15) * 4;

    for (int k0 = 0; k0 < FDIM; k0 += 16) {
        int r = row0 + ar;
        float4 v0 = make_float4(0.f, 0.f, 0.f, 0.f), v1 = v0;
        if (r < M) {
            const float4* xp = (const float4*)&x[(size_t)r * FDIM + k0 + akq];
            v0 = xp[0];
            v1 = xp[1];
        }
        As[akq + 0][ar] = v0.x; As[akq + 1][ar] = v0.y;
        As[akq + 2][ar] = v0.z; As[akq + 3][ar] = v0.w;
        As[akq + 4][ar] = v1.x; As[akq + 5][ar] = v1.y;
        As[akq + 6][ar] = v1.z; As[akq + 7][ar] = v1.w;

        *(float4*)&Bs[bk][bn] = *(const float4*)&W[(size_t)(k0 + bk) * FDIM + col0 + bn];
        __syncthreads();

#pragma unroll
        for (int kk = 0; kk < 16; kk++) {
            float a[8], b[4];
            *(float4*)&a[0] = *(const float4*)&As[kk][ty * 8];
            *(float4*)&a[4] = *(const float4*)&As[kk][ty * 8 + 4];
            *(float4*)&b[0] = *(const float4*)&Bs[kk][tx * 4];
#pragma unroll
            for (int i = 0; i < 8; i++)
#pragma unroll
                for (int j = 0; j < 4; j++) acc[i][j] = fmaf(a[i], b[j], acc[i][j]);
        }
        __syncthreads();
    }
#pragma unroll
    for (int i = 0; i < 8; i++) {
        int r = row0 + ty * 8 + i;
        if (r < M)
            *(float4*)&g_h[(size_t)r * FDIM + col0 + tx * 4] =
                make_float4(acc[i][0], acc[i][1], acc[i][2], acc[i][3]);
    }
}

// ---------------------------------------------------------------------------
// Per-node attention dots: one warp per node.
// ---------------------------------------------------------------------------
__global__ void adot_kernel(const float* __restrict__ att_src,
                            const float* __restrict__ att_dst, int N) {
    int gw = (blockIdx.x * blockDim.x + threadIdx.x) >> 5;
    int lane = threadIdx.x & 31;
    if (gw >= N) return;
    const float4* hp = (const float4*)(g_h + (size_t)gw * FDIM);
    float4 v0 = hp[lane * 2], v1 = hp[lane * 2 + 1];
    int head = lane >> 3;
    int off = head * HEAD_DIM + (lane & 7) * 8;
    const float4* sp = (const float4*)(att_src + off);
    const float4* dp = (const float4*)(att_dst + off);
    float4 s0 = sp[0], s1 = sp[1];
    float4 d0 = dp[0], d1 = dp[1];
    float ps = v0.x*s0.x + v0.y*s0.y + v0.z*s0.z + v0.w*s0.w
             + v1.x*s1.x + v1.y*s1.y + v1.z*s1.z + v1.w*s1.w;
    float pd = v0.x*d0.x + v0.y*d0.y + v0.z*d0.z + v0.w*d0.w
             + v1.x*d1.x + v1.y*d1.y + v1.z*d1.z + v1.w*d1.w;
#pragma unroll
    for (int sh = 1; sh < 8; sh <<= 1) {
        ps += __shfl_xor_sync(0xFFFFFFFF, ps, sh);
        pd += __shfl_xor_sync(0xFFFFFFFF, pd, sh);
    }
    if ((lane & 7) == 0) {
        g_asrc[gw * HEADS + head] = ps;
        g_adst[gw * HEADS + head] = pd;
    }
}

// ---------------------------------------------------------------------------
// Fused per-node softmax + aggregation. One warp per destination node.
// Pass1: segment max. Pass2: sum exp. Pass3: weighted gather of h[src].
// No atomics; out written exactly once (bias folded in).
// ---------------------------------------------------------------------------
__global__ void agg_kernel(float* __restrict__ out, const float* __restrict__ bias, int N) {
    int d = (blockIdx.x * blockDim.x + threadIdx.x) >> 5;
    int lane = threadIdx.x & 31;
    if (d >= N) return;
    int row = g_rowstart[d];
    int re  = g_rowstart[d + 1];
    float4 ad = *(const float4*)&g_adst[d * 4];

    // Pass 1: max over edges
    float4 mx = make_float4(-1e30f, -1e30f, -1e30f, -1e30f);
    for (int i = row + lane; i < re; i += 32) {
        int s = g_esrc[i];
        float4 as = *(const float4*)&g_asrc[s * 4];
        mx.x = fmaxf(mx.x, lrelu(as.x + ad.x));
        mx.y = fmaxf(mx.y, lrelu(as.y + ad.y));
        mx.z = fmaxf(mx.z, lrelu(as.z + ad.z));
        mx.w = fmaxf(mx.w, lrelu(as.w + ad.w));
    }
#pragma unroll
    for (int sh = 16; sh; sh >>= 1) {
        mx.x = fmaxf(mx.x, __shfl_xor_sync(0xFFFFFFFF, mx.x, sh));
        mx.y = fmaxf(mx.y, __shfl_xor_sync(0xFFFFFFFF, mx.y, sh));
        mx.z = fmaxf(mx.z, __shfl_xor_sync(0xFFFFFFFF, mx.z, sh));
        mx.w = fmaxf(mx.w, __shfl_xor_sync(0xFFFFFFFF, mx.w, sh));
    }

    // Pass 2: sum of exp
    float4 sm = make_float4(0.f, 0.f, 0.f, 0.f);
    for (int i = row + lane; i < re; i += 32) {
        int s = g_esrc[i];
        float4 as = *(const float4*)&g_asrc[s * 4];
        sm.x += __expf(lrelu(as.x + ad.x) - mx.x);
        sm.y += __expf(lrelu(as.y + ad.y) - mx.y);
        sm.z += __expf(lrelu(as.z + ad.z) - mx.z);
        sm.w += __expf(lrelu(as.w + ad.w) - mx.w);
    }
#pragma unroll
    for (int sh = 16; sh; sh >>= 1) {
        sm.x += __shfl_xor_sync(0xFFFFFFFF, sm.x, sh);
        sm.y += __shfl_xor_sync(0xFFFFFFFF, sm.y, sh);
        sm.z += __shfl_xor_sync(0xFFFFFFFF, sm.z, sh);
        sm.w += __shfl_xor_sync(0xFFFFFFFF, sm.w, sh);
    }
    float4 rs = make_float4(1.f / sm.x, 1.f / sm.y, 1.f / sm.z, 1.f / sm.w);

    // Pass 3: weighted accumulation of h[src]
    float4 acc0 = make_float4(0.f, 0.f, 0.f, 0.f);
    float4 acc1 = acc0;
    for (int i = row; i < re; i++) {
        int s = g_esrc[i];                               // broadcast load
        float4 as = *(const float4*)&g_asrc[s * 4];      // broadcast load
        float al0 = __expf(lrelu(as.x + ad.x) - mx.x) * rs.x;
        float al1 = __expf(lrelu(as.y + ad.y) - mx.y) * rs.y;
        float al2 = __expf(lrelu(as.z + ad.z) - mx.z) * rs.z;
        float al3 = __expf(lrelu(as.w + ad.w) - mx.w) * rs.w;
        float aA = (lane < 16) ? al0 : al1;
        float aB = (lane < 16) ? al2 : al3;
        const float4* hp = (const float4*)(g_h + (size_t)s * FDIM);
        float4 h0 = hp[lane];
        float4 h1 = hp[lane + 32];
        acc0.x = fmaf(aA, h0.x, acc0.x); acc0.y = fmaf(aA, h0.y, acc0.y);
        acc0.z = fmaf(aA, h0.z, acc0.z); acc0.w = fmaf(aA, h0.w, acc0.w);
        acc1.x = fmaf(aB, h1.x, acc1.x); acc1.y = fmaf(aB, h1.y, acc1.y);
        acc1.z = fmaf(aB, h1.z, acc1.z); acc1.w = fmaf(aB, h1.w, acc1.w);
    }
    const float4* bp = (const float4*)bias;
    float4 b0 = bp[lane], b1 = bp[lane + 32];
    float4 o0 = make_float4(acc0.x + b0.x, acc0.y + b0.y, acc0.z + b0.z, acc0.w + b0.w);
    float4 o1 = make_float4(acc1.x + b1.x, acc1.y + b1.y, acc1.z + b1.z, acc1.w + b1.w);
    float4* op = (float4*)(out + (size_t)d * FDIM);
    op[lane] = o0;
    op[lane + 32] = o1;
}

// ---------------------------------------------------------------------------
extern "C" void kernel_launch(void* const* d_in, const int* in_sizes, int n_in,
                              void* d_out, int out_size) {
    const float* x        = (const float*)d_in[0];
    const void*  ei       = d_in[1];
    const float* W        = (const float*)d_in[2];
    const float* att_src  = (const float*)d_in[3];
    const float* att_dst  = (const float*)d_in[4];
    const float* bias     = (const float*)d_in[5];
    float* out = (float*)d_out;

    int N = in_sizes[0] / FDIM;
    int E = in_sizes[1] / 2;
    int ET = E + N;

    detect_kernel<<<1, 1>>>((const unsigned int*)ei, in_sizes[1]);
    zero_kernel<<<(N + 255) / 256, 256>>>(N);
    hist_kernel<<<(ET + 255) / 256, 256>>>(ei, E, N);
    scan_kernel<<<1, SCAN_T>>>(N);
    fill_kernel<<<(ET + 255) / 256, 256>>>(ei, E, N);

    dim3 ggrid((N + 127) / 128, FDIM / 64);
    gemm_kernel<<<ggrid, 256>>>(x, W, N);

    adot_kernel<<<(N * 32 + 255) / 256, 256>>>(att_src, att_dst, N);

    agg_kernel<<<((size_t)N * 32 + 255) / 256, 256>>>(out, bias, N);
}

// round 4
// speedup vs baseline: 1.5937x; 1.2335x over previous
#include <cuda_runtime.h>

#define FDIM 256
#define HEADS 4
#define HEAD_DIM 64
#define NEG_SLOPE 0.2f
#define MAX_N 50000
#define MAX_E 800000
#define SCAN_B 1024
#define MAX_BLKS ((MAX_N + SCAN_B - 1) / SCAN_B)

// Scratch (static __device__ — allocation-free per harness rules)
__device__ __align__(16) float g_h[MAX_N * FDIM];        // 51.2 MB, h = xW
__device__ __align__(16) float g_asrc[MAX_N * HEADS];
__device__ __align__(16) float g_adst[MAX_N * HEADS];
__device__ int g_count[MAX_N];
__device__ int g_rowstart[MAX_N + 1];
__device__ int g_cursor[MAX_N];
__device__ int g_esrc[MAX_E + MAX_N];
__device__ int g_blocksum[MAX_BLKS];
__device__ int g_blockoff[MAX_BLKS + 1];
__device__ int g_is64;

__device__ __forceinline__ float lrelu(float v) {
    return v > 0.0f ? v : NEG_SLOPE * v;
}

// Load edge index at position pos, dtype-agnostic (int32 vs int64), clamped.
__device__ __forceinline__ int load_idx(const void* ei, long long pos, int is64, int N) {
    int v;
    if (is64) v = (int)((const long long*)ei)[pos];
    else      v = ((const int*)ei)[pos];
    v = v < 0 ? 0 : (v >= N ? N - 1 : v);
    return v;
}

// ---------------------------------------------------------------------------
// Detect int64 vs int32: for int64 (values < 2^31) all odd words are zero.
// 128 threads each check one odd word; ballot.
// ---------------------------------------------------------------------------
__global__ void detect_kernel(const unsigned int* __restrict__ w, int nwords) {
    __shared__ int nz[4];
    int t = threadIdx.x;
    if (t < 4 && threadIdx.x < 4) nz[t] = 0;
    __syncthreads();
    int idx = 2 * t + 1;
    int bad = (idx < nwords && idx < 256 * 2) ? (w[idx] != 0u) : 0;
    if (bad) nz[0] = 1;
    __syncthreads();
    if (t == 0) g_is64 = !nz[0];
}

__global__ void zero_kernel(int N) {
    int i = blockIdx.x * blockDim.x + threadIdx.x;
    if (i < N) g_count[i] = 0;
}

// ---------------------------------------------------------------------------
// Histogram of destination degrees (incl. self loops)
// ---------------------------------------------------------------------------
__global__ void hist_kernel(const void* __restrict__ ei, int E, int N) {
    int e = blockIdx.x * blockDim.x + threadIdx.x;
    int ET = E + N;
    if (e >= ET) return;
    int d = (e < E) ? load_idx(ei, (long long)E + e, g_is64, N) : e - E;
    atomicAdd(&g_count[d], 1);
}

// ---------------------------------------------------------------------------
// Scan phase 1: per-block sum of g_count segments
// ---------------------------------------------------------------------------
__global__ void scan1_kernel(int N) {
    __shared__ int sh[32];
    int i = blockIdx.x * SCAN_B + threadIdx.x;
    int v = (i < N) ? g_count[i] : 0;
#pragma unroll
    for (int sft = 16; sft; sft >>= 1) v += __shfl_xor_sync(0xFFFFFFFF, v, sft);
    if ((threadIdx.x & 31) == 0) sh[threadIdx.x >> 5] = v;
    __syncthreads();
    if (threadIdx.x < 32) {
        int w = (threadIdx.x < SCAN_B / 32) ? sh[threadIdx.x] : 0;
#pragma unroll
        for (int sft = 16; sft; sft >>= 1) w += __shfl_xor_sync(0xFFFFFFFF, w, sft);
        if (threadIdx.x == 0) g_blocksum[blockIdx.x] = w;
    }
}

// ---------------------------------------------------------------------------
// Scan phase 2: exclusive scan of block sums (tiny, 1 block)
// ---------------------------------------------------------------------------
__global__ void scan2_kernel(int nblks) {
    __shared__ int sh[MAX_BLKS];
    int t = threadIdx.x;
    if (t < nblks) sh[t] = g_blocksum[t];
    __syncthreads();
    if (t == 0) {
        int run = 0;
        for (int b = 0; b < nblks; b++) {
            g_blockoff[b] = run;
            run += sh[b];
        }
        g_blockoff[nblks] = run;
    }
}

// ---------------------------------------------------------------------------
// Scan phase 3: local exclusive scan + block offset -> rowstart/cursor
// ---------------------------------------------------------------------------
__global__ void scan3_kernel(int N) {
    __shared__ int warpsum[32];
    int i = blockIdx.x * SCAN_B + threadIdx.x;
    int lane = threadIdx.x & 31, wid = threadIdx.x >> 5;
    int v = (i < N) ? g_count[i] : 0;
    // inclusive warp scan
    int x = v;
#pragma unroll
    for (int sft = 1; sft < 32; sft <<= 1) {
        int y = __shfl_up_sync(0xFFFFFFFF, x, sft);
        if (lane >= sft) x += y;
    }
    if (lane == 31) warpsum[wid] = x;
    __syncthreads();
    if (wid == 0) {
        int w = (lane < SCAN_B / 32) ? warpsum[lane] : 0;
#pragma unroll
        for (int sft = 1; sft < 32; sft <<= 1) {
            int y = __shfl_up_sync(0xFFFFFFFF, w, sft);
            if (lane >= sft) w += y;
        }
        if (lane < SCAN_B / 32) warpsum[lane] = w;
    }
    __syncthreads();
    int excl = x - v + (wid ? warpsum[wid - 1] : 0) + g_blockoff[blockIdx.x];
    if (i < N) {
        g_rowstart[i] = excl;
        g_cursor[i] = excl;
        if (i == N - 1) g_rowstart[N] = excl + v;
    }
}

// ---------------------------------------------------------------------------
// Fill CSR: scatter src indices into dst-grouped buckets
// ---------------------------------------------------------------------------
__global__ void fill_kernel(const void* __restrict__ ei, int E, int N) {
    int e = blockIdx.x * blockDim.x + threadIdx.x;
    int ET = E + N;
    if (e >= ET) return;
    int is64 = g_is64;
    int s, d;
    if (e < E) {
        s = load_idx(ei, e, is64, N);
        d = load_idx(ei, (long long)E + e, is64, N);
    } else s = d = e - E;
    int pos = atomicAdd(&g_cursor[d], 1);
    g_esrc[pos] = s;
}

// ---------------------------------------------------------------------------
// GEMM: g_h[M,256] = x[M,256] @ W[256,256]. BM=128, BN=64, BK=16,
// 256 threads, 8x4 accumulators per thread.
// ---------------------------------------------------------------------------
__global__ void gemm_kernel(const float* __restrict__ x, const float* __restrict__ W, int M) {
    __shared__ float As[16][132];  // [k][m], padded
    __shared__ float Bs[16][64];   // [k][n]
    int tid = threadIdx.x;
    int tx = tid & 15, ty = tid >> 4;
    int row0 = blockIdx.x * 128;
    int col0 = blockIdx.y * 64;

    float acc[8][4];
#pragma unroll
    for (int i = 0; i < 8; i++)
#pragma unroll
        for (int j = 0; j < 4; j++) acc[i][j] = 0.0f;

    int ar = tid >> 1;
    int akq = (tid & 1) * 8;
    int bk = tid >> 4;
    int bn = (tid & 15) * 4;

    for (int k0 = 0; k0 < FDIM; k0 += 16) {
        int r = row0 + ar;
        float4 v0 = make_float4(0.f, 0.f, 0.f, 0.f), v1 = v0;
        if (r < M) {
            const float4* xp = (const float4*)&x[(size_t)r * FDIM + k0 + akq];
            v0 = xp[0];
            v1 = xp[1];
        }
        As[akq + 0][ar] = v0.x; As[akq + 1][ar] = v0.y;
        As[akq + 2][ar] = v0.z; As[akq + 3][ar] = v0.w;
        As[akq + 4][ar] = v1.x; As[akq + 5][ar] = v1.y;
        As[akq + 6][ar] = v1.z; As[akq + 7][ar] = v1.w;

        *(float4*)&Bs[bk][bn] = *(const float4*)&W[(size_t)(k0 + bk) * FDIM + col0 + bn];
        __syncthreads();

#pragma unroll
        for (int kk = 0; kk < 16; kk++) {
            float a[8], b[4];
            *(float4*)&a[0] = *(const float4*)&As[kk][ty * 8];
            *(float4*)&a[4] = *(const float4*)&As[kk][ty * 8 + 4];
            *(float4*)&b[0] = *(const float4*)&Bs[kk][tx * 4];
#pragma unroll
            for (int i = 0; i < 8; i++)
#pragma unroll
                for (int j = 0; j < 4; j++) acc[i][j] = fmaf(a[i], b[j], acc[i][j]);
        }
        __syncthreads();
    }
#pragma unroll
    for (int i = 0; i < 8; i++) {
        int r = row0 + ty * 8 + i;
        if (r < M)
            *(float4*)&g_h[(size_t)r * FDIM + col0 + tx * 4] =
                make_float4(acc[i][0], acc[i][1], acc[i][2], acc[i][3]);
    }
}

// ---------------------------------------------------------------------------
// Per-node attention dots: one warp per node.
// ---------------------------------------------------------------------------
__global__ void adot_kernel(const float* __restrict__ att_src,
                            const float* __restrict__ att_dst, int N) {
    int gw = (blockIdx.x * blockDim.x + threadIdx.x) >> 5;
    int lane = threadIdx.x & 31;
    if (gw >= N) return;
    const float4* hp = (const float4*)(g_h + (size_t)gw * FDIM);
    float4 v0 = hp[lane * 2], v1 = hp[lane * 2 + 1];
    int head = lane >> 3;
    int off = head * HEAD_DIM + (lane & 7) * 8;
    const float4* sp = (const float4*)(att_src + off);
    const float4* dp = (const float4*)(att_dst + off);
    float4 s0 = sp[0], s1 = sp[1];
    float4 d0 = dp[0], d1 = dp[1];
    float ps = v0.x*s0.x + v0.y*s0.y + v0.z*s0.z + v0.w*s0.w
             + v1.x*s1.x + v1.y*s1.y + v1.z*s1.z + v1.w*s1.w;
    float pd = v0.x*d0.x + v0.y*d0.y + v0.z*d0.z + v0.w*d0.w
             + v1.x*d1.x + v1.y*d1.y + v1.z*d1.z + v1.w*d1.w;
#pragma unroll
    for (int sh = 1; sh < 8; sh <<= 1) {
        ps += __shfl_xor_sync(0xFFFFFFFF, ps, sh);
        pd += __shfl_xor_sync(0xFFFFFFFF, pd, sh);
    }
    if ((lane & 7) == 0) {
        g_asrc[gw * HEADS + head] = ps;
        g_adst[gw * HEADS + head] = pd;
    }
}

// ---------------------------------------------------------------------------
// Fused per-node softmax + aggregation. One warp per destination node.
// ---------------------------------------------------------------------------
__global__ void agg_kernel(float* __restrict__ out, const float* __restrict__ bias, int N) {
    int d = (blockIdx.x * blockDim.x + threadIdx.x) >> 5;
    int lane = threadIdx.x & 31;
    if (d >= N) return;
    int row = g_rowstart[d];
    int re  = g_rowstart[d + 1];
    float4 ad = *(const float4*)&g_adst[d * 4];

    // Pass 1: max over edges
    float4 mx = make_float4(-1e30f, -1e30f, -1e30f, -1e30f);
    for (int i = row + lane; i < re; i += 32) {
        int s = g_esrc[i];
        float4 as = *(const float4*)&g_asrc[s * 4];
        mx.x = fmaxf(mx.x, lrelu(as.x + ad.x));
        mx.y = fmaxf(mx.y, lrelu(as.y + ad.y));
        mx.z = fmaxf(mx.z, lrelu(as.z + ad.z));
        mx.w = fmaxf(mx.w, lrelu(as.w + ad.w));
    }
#pragma unroll
    for (int sh = 16; sh; sh >>= 1) {
        mx.x = fmaxf(mx.x, __shfl_xor_sync(0xFFFFFFFF, mx.x, sh));
        mx.y = fmaxf(mx.y, __shfl_xor_sync(0xFFFFFFFF, mx.y, sh));
        mx.z = fmaxf(mx.z, __shfl_xor_sync(0xFFFFFFFF, mx.z, sh));
        mx.w = fmaxf(mx.w, __shfl_xor_sync(0xFFFFFFFF, mx.w, sh));
    }

    // Pass 2: sum of exp
    float4 sm = make_float4(0.f, 0.f, 0.f, 0.f);
    for (int i = row + lane; i < re; i += 32) {
        int s = g_esrc[i];
        float4 as = *(const float4*)&g_asrc[s * 4];
        sm.x += __expf(lrelu(as.x + ad.x) - mx.x);
        sm.y += __expf(lrelu(as.y + ad.y) - mx.y);
        sm.z += __expf(lrelu(as.z + ad.z) - mx.z);
        sm.w += __expf(lrelu(as.w + ad.w) - mx.w);
    }
#pragma unroll
    for (int sh = 16; sh; sh >>= 1) {
        sm.x += __shfl_xor_sync(0xFFFFFFFF, sm.x, sh);
        sm.y += __shfl_xor_sync(0xFFFFFFFF, sm.y, sh);
        sm.z += __shfl_xor_sync(0xFFFFFFFF, sm.z, sh);
        sm.w += __shfl_xor_sync(0xFFFFFFFF, sm.w, sh);
    }
    float4 rs = make_float4(1.f / sm.x, 1.f / sm.y, 1.f / sm.z, 1.f / sm.w);

    // Pass 3: weighted accumulation of h[src]
    float4 acc0 = make_float4(0.f, 0.f, 0.f, 0.f);
    float4 acc1 = acc0;
    for (int i = row; i < re; i++) {
        int s = g_esrc[i];                               // broadcast load
        float4 as = *(const float4*)&g_asrc[s * 4];      // broadcast load
        float al0 = __expf(lrelu(as.x + ad.x) - mx.x) * rs.x;
        float al1 = __expf(lrelu(as.y + ad.y) - mx.y) * rs.y;
        float al2 = __expf(lrelu(as.z + ad.z) - mx.z) * rs.z;
        float al3 = __expf(lrelu(as.w + ad.w) - mx.w) * rs.w;
        float aA = (lane < 16) ? al0 : al1;
        float aB = (lane < 16) ? al2 : al3;
        const float4* hp = (const float4*)(g_h + (size_t)s * FDIM);
        float4 h0 = hp[lane];
        float4 h1 = hp[lane + 32];
        acc0.x = fmaf(aA, h0.x, acc0.x); acc0.y = fmaf(aA, h0.y, acc0.y);
        acc0.z = fmaf(aA, h0.z, acc0.z); acc0.w = fmaf(aA, h0.w, acc0.w);
        acc1.x = fmaf(aB, h1.x, acc1.x); acc1.y = fmaf(aB, h1.y, acc1.y);
        acc1.z = fmaf(aB, h1.z, acc1.z); acc1.w = fmaf(aB, h1.w, acc1.w);
    }
    const float4* bp = (const float4*)bias;
    float4 b0 = bp[lane], b1 = bp[lane + 32];
    float4 o0 = make_float4(acc0.x + b0.x, acc0.y + b0.y, acc0.z + b0.z, acc0.w + b0.w);
    float4 o1 = make_float4(acc1.x + b1.x, acc1.y + b1.y, acc1.z + b1.z, acc1.w + b1.w);
    float4* op = (float4*)(out + (size_t)d * FDIM);
    op[lane] = o0;
    op[lane + 32] = o1;
}

// ---------------------------------------------------------------------------
extern "C" void kernel_launch(void* const* d_in, const int* in_sizes, int n_in,
                              void* d_out, int out_size) {
    const float* x        = (const float*)d_in[0];
    const void*  ei       = d_in[1];
    const float* W        = (const float*)d_in[2];
    const float* att_src  = (const float*)d_in[3];
    const float* att_dst  = (const float*)d_in[4];
    const float* bias     = (const float*)d_in[5];
    float* out = (float*)d_out;

    int N = in_sizes[0] / FDIM;
    int E = in_sizes[1] / 2;
    int ET = E + N;
    int nblks = (N + SCAN_B - 1) / SCAN_B;

    detect_kernel<<<1, 128>>>((const unsigned int*)ei, in_sizes[1]);
    zero_kernel<<<(N + 255) / 256, 256>>>(N);
    hist_kernel<<<(ET + 255) / 256, 256>>>(ei, E, N);
    scan1_kernel<<<nblks, SCAN_B>>>(N);
    scan2_kernel<<<1, 64>>>(nblks);
    scan3_kernel<<<nblks, SCAN_B>>>(N);
    fill_kernel<<<(ET + 255) / 256, 256>>>(ei, E, N);

    dim3 ggrid((N + 127) / 128, FDIM / 64);
    gemm_kernel<<<ggrid, 256>>>(x, W, N);

    adot_kernel<<<(N * 32 + 255) / 256, 256>>>(att_src, att_dst, N);

    agg_kernel<<<((size_t)N * 32 + 255) / 256, 256>>>(out, bias, N);
}

// round 6
// speedup vs baseline: 1.8100x; 1.1357x over previous
#include <cuda_runtime.h>
#include <cuda_bf16.h>
#include <cuda_fp16.h>
#include <mma.h>
#include <cstdint>

using namespace nvcuda;

#define FDIM 256
#define HEADS 4
#define HEAD_DIM 64
#define NEG_SLOPE 0.2f
#define MAX_N 50000
#define MAX_E 800000
#define SCAN_B 1024
#define MAX_BLKS ((MAX_N + SCAN_B - 1) / SCAN_B)

// GEMM tile config
#define BM 64
#define BN 256
#define BK 64
#define LDA 72    // bf16 elems per A smem row (64 + 8 pad)
#define LDB 264   // bf16 elems per B smem row (256 + 8 pad)
#define LDO 260   // fp32 elems per epilogue smem row

// ---------------- scratch (static __device__, allocation-free) --------------
__device__ __align__(16) __half g_h16[MAX_N * FDIM];            // 25.6 MB
__device__ __align__(16) float g_asrc[MAX_N * HEADS];
__device__ __align__(16) float g_adst[MAX_N * HEADS];
__device__ __align__(16) float g_anum[(MAX_E + MAX_N) * HEADS]; // 13.6 MB
__device__ int g_count[MAX_N];
__device__ int g_rowstart[MAX_N + 1];
__device__ int g_cursor[MAX_N];
__device__ int g_esrc[MAX_E + MAX_N];
__device__ int g_blocksum[MAX_BLKS];
__device__ int g_blockoff[MAX_BLKS + 1];
__device__ int g_is64;

__device__ __forceinline__ float lrelu(float v) { return v > 0.0f ? v : NEG_SLOPE * v; }

__device__ __forceinline__ int load_idx(const void* ei, long long pos, int is64, int N) {
    int v;
    if (is64) v = (int)((const long long*)ei)[pos];
    else      v = ((const int*)ei)[pos];
    v = v < 0 ? 0 : (v >= N ? N - 1 : v);
    return v;
}

__device__ __forceinline__ uint32_t pack2bf(float a, float b) {
    __nv_bfloat162 t = __floats2bfloat162_rn(a, b);
    return *(uint32_t*)&t;
}

// ---------------------------------------------------------------------------
__global__ void detect_kernel(const unsigned int* __restrict__ w, int nwords) {
    __shared__ int nz;
    if (threadIdx.x == 0) nz = 0;
    __syncthreads();
    int idx = 2 * threadIdx.x + 1;
    if (idx < nwords && idx < 512 && w[idx] != 0u) nz = 1;
    __syncthreads();
    if (threadIdx.x == 0) g_is64 = !nz;
}

__global__ void zero_kernel(int N) {
    int i = blockIdx.x * blockDim.x + threadIdx.x;
    if (i < N) g_count[i] = 0;
}

__global__ void hist_kernel(const void* __restrict__ ei, int E, int N) {
    int e = blockIdx.x * blockDim.x + threadIdx.x;
    int ET = E + N;
    if (e >= ET) return;
    int d = (e < E) ? load_idx(ei, (long long)E + e, g_is64, N) : e - E;
    atomicAdd(&g_count[d], 1);
}

__global__ void scan1_kernel(int N) {
    __shared__ int sh[32];
    int i = blockIdx.x * SCAN_B + threadIdx.x;
    int v = (i < N) ? g_count[i] : 0;
#pragma unroll
    for (int sft = 16; sft; sft >>= 1) v += __shfl_xor_sync(0xFFFFFFFF, v, sft);
    if ((threadIdx.x & 31) == 0) sh[threadIdx.x >> 5] = v;
    __syncthreads();
    if (threadIdx.x < 32) {
        int w = (threadIdx.x < SCAN_B / 32) ? sh[threadIdx.x] : 0;
#pragma unroll
        for (int sft = 16; sft; sft >>= 1) w += __shfl_xor_sync(0xFFFFFFFF, w, sft);
        if (threadIdx.x == 0) g_blocksum[blockIdx.x] = w;
    }
}

__global__ void scan2_kernel(int nblks) {
    if (threadIdx.x == 0) {
        int run = 0;
        for (int b = 0; b < nblks; b++) {
            g_blockoff[b] = run;
            run += g_blocksum[b];
        }
        g_blockoff[nblks] = run;
    }
}

__global__ void scan3_kernel(int N) {
    __shared__ int warpsum[32];
    int i = blockIdx.x * SCAN_B + threadIdx.x;
    int lane = threadIdx.x & 31, wid = threadIdx.x >> 5;
    int v = (i < N) ? g_count[i] : 0;
    int x = v;
#pragma unroll
    for (int sft = 1; sft < 32; sft <<= 1) {
        int y = __shfl_up_sync(0xFFFFFFFF, x, sft);
        if (lane >= sft) x += y;
    }
    if (lane == 31) warpsum[wid] = x;
    __syncthreads();
    if (wid == 0) {
        int w = (lane < SCAN_B / 32) ? warpsum[lane] : 0;
#pragma unroll
        for (int sft = 1; sft < 32; sft <<= 1) {
            int y = __shfl_up_sync(0xFFFFFFFF, w, sft);
            if (lane >= sft) w += y;
        }
        if (lane < SCAN_B / 32) warpsum[lane] = w;
    }
    __syncthreads();
    int excl = x - v + (wid ? warpsum[wid - 1] : 0) + g_blockoff[blockIdx.x];
    if (i < N) {
        g_rowstart[i] = excl;
        g_cursor[i] = excl;
        if (i == N - 1) g_rowstart[N] = excl + v;
    }
}

__global__ void fill_kernel(const void* __restrict__ ei, int E, int N) {
    int e = blockIdx.x * blockDim.x + threadIdx.x;
    int ET = E + N;
    if (e >= ET) return;
    int is64 = g_is64;
    int s, d;
    if (e < E) {
        s = load_idx(ei, e, is64, N);
        d = load_idx(ei, (long long)E + e, is64, N);
    } else s = d = e - E;
    int pos = atomicAdd(&g_cursor[d], 1);
    g_esrc[pos] = s;
}

// ---------------------------------------------------------------------------
// WMMA bf16 split GEMM + fused epilogue.
// CTA: 256 threads (8 warps, 2x4 warp grid of 32x64 tiles), tile 64x256, BK=64.
// h = x@W via Ahi*Bhi + Ahi*Blo + Alo*Bhi (fp32 acc).
// Epilogue: acc->smem fp32, per-row att dots, h stored fp16.
// ---------------------------------------------------------------------------
#define GEMM_SMEM ((2 * BM * LDA + 2 * BK * LDB) * 2)  // 86016 bytes

__global__ __launch_bounds__(256, 2)
void gemm_tc_kernel(const float* __restrict__ x, const float* __restrict__ W,
                    const float* __restrict__ att_src,
                    const float* __restrict__ att_dst, int M) {
    extern __shared__ char smem[];
    __nv_bfloat16* Ahi = (__nv_bfloat16*)smem;
    __nv_bfloat16* Alo = Ahi + BM * LDA;
    __nv_bfloat16* Bhi = Alo + BM * LDA;
    __nv_bfloat16* Blo = Bhi + BK * LDB;
    float* s_out = (float*)smem;  // reused after mainloop
    __shared__ float s_src[FDIM], s_dst[FDIM];

    int tid = threadIdx.x;
    int wid = tid >> 5;
    int wm = wid >> 2, wn = wid & 3;   // warp tile (wm*32, wn*64)
    int row0 = blockIdx.x * BM;

    s_src[tid] = att_src[tid];
    s_dst[tid] = att_dst[tid];

    wmma::fragment<wmma::accumulator, 16, 16, 16, float> c[2][4];
#pragma unroll
    for (int i = 0; i < 2; i++)
#pragma unroll
        for (int j = 0; j < 4; j++) wmma::fill_fragment(c[i][j], 0.0f);

    int ar = tid >> 2, acg = (tid & 3) * 16;     // A fill: row, 16-col group
    int bk = tid >> 2, bcg = (tid & 3) * 64;     // B fill: k-row, 64-col group

    for (int c4 = 0; c4 < 4; c4++) {
        int k0 = c4 * BK;
        // A tile: x[row0+ar][k0+acg..+16) -> hi/lo bf16
        {
            int r = row0 + ar;
            const float4* xp = (r < M) ? (const float4*)&x[(size_t)r * FDIM + k0 + acg] : nullptr;
#pragma unroll
            for (int j = 0; j < 4; j++) {
                float4 v = xp ? xp[j] : make_float4(0.f, 0.f, 0.f, 0.f);
                __nv_bfloat16 h0 = __float2bfloat16_rn(v.x), h1 = __float2bfloat16_rn(v.y);
                __nv_bfloat16 h2 = __float2bfloat16_rn(v.z), h3 = __float2bfloat16_rn(v.w);
                uint2 phi, plo;
                phi.x = pack2bf(__bfloat162float(h0), __bfloat162float(h1));
                phi.y = pack2bf(__bfloat162float(h2), __bfloat162float(h3));
                plo.x = pack2bf(v.x - __bfloat162float(h0), v.y - __bfloat162float(h1));
                plo.y = pack2bf(v.z - __bfloat162float(h2), v.w - __bfloat162float(h3));
                *(uint2*)&Ahi[ar * LDA + acg + j * 4] = phi;
                *(uint2*)&Alo[ar * LDA + acg + j * 4] = plo;
            }
        }
        // B tile: W[k0+bk][bcg..+64) -> hi/lo bf16
        {
            const float4* wp = (const float4*)&W[(size_t)(k0 + bk) * FDIM + bcg];
#pragma unroll
            for (int j = 0; j < 16; j++) {
                float4 v = wp[j];
                __nv_bfloat16 h0 = __float2bfloat16_rn(v.x), h1 = __float2bfloat16_rn(v.y);
                __nv_bfloat16 h2 = __float2bfloat16_rn(v.z), h3 = __float2bfloat16_rn(v.w);
                uint2 phi, plo;
                phi.x = pack2bf(__bfloat162float(h0), __bfloat162float(h1));
                phi.y = pack2bf(__bfloat162float(h2), __bfloat162float(h3));
                plo.x = pack2bf(v.x - __bfloat162float(h0), v.y - __bfloat162float(h1));
                plo.y = pack2bf(v.z - __bfloat162float(h2), v.w - __bfloat162float(h3));
                *(uint2*)&Bhi[bk * LDB + bcg + j * 4] = phi;
                *(uint2*)&Blo[bk * LDB + bcg + j * 4] = plo;
            }
        }
        __syncthreads();

#pragma unroll
        for (int ks = 0; ks < 4; ks++) {
            wmma::fragment<wmma::matrix_a, 16, 16, 16, __nv_bfloat16, wmma::row_major> ah[2], al[2];
#pragma unroll
            for (int i = 0; i < 2; i++) {
                wmma::load_matrix_sync(ah[i], &Ahi[(wm * 32 + i * 16) * LDA + ks * 16], LDA);
                wmma::load_matrix_sync(al[i], &Alo[(wm * 32 + i * 16) * LDA + ks * 16], LDA);
            }
#pragma unroll
            for (int j = 0; j < 4; j++) {
                wmma::fragment<wmma::matrix_b, 16, 16, 16, __nv_bfloat16, wmma::row_major> bh, bl;
                wmma::load_matrix_sync(bh, &Bhi[(ks * 16) * LDB + wn * 64 + j * 16], LDB);
                wmma::load_matrix_sync(bl, &Blo[(ks * 16) * LDB + wn * 64 + j * 16], LDB);
#pragma unroll
                for (int i = 0; i < 2; i++) {
                    wmma::mma_sync(c[i][j], ah[i], bh, c[i][j]);
                    wmma::mma_sync(c[i][j], ah[i], bl, c[i][j]);
                    wmma::mma_sync(c[i][j], al[i], bh, c[i][j]);
                }
            }
        }
        __syncthreads();
    }

    // ---- epilogue: acc -> smem fp32 ----
#pragma unroll
    for (int i = 0; i < 2; i++)
#pragma unroll
        for (int j = 0; j < 4; j++)
            wmma::store_matrix_sync(&s_out[(wm * 32 + i * 16) * LDO + wn * 64 + j * 16],
                                    c[i][j], LDO, wmma::mem_row_major);
    __syncthreads();

    // 128 threads: thread t handles row t/2, cols half*(128)..+128 (2 heads)
    if (tid < 128) {
        int r = tid >> 1, half = tid & 1;
        int row = row0 + r;
        if (row < M) {
            const float* so = s_out + r * LDO + half * 128;
            const float* sp = s_src + half * 128;
            const float* dp = s_dst + half * 128;
            float psA = 0.f, pdA = 0.f, psB = 0.f, pdB = 0.f;
            uint32_t pk[64];
#pragma unroll
            for (int cc = 0; cc < 64; cc++) {
                float v = so[cc];
                psA = fmaf(v, sp[cc], psA);
                pdA = fmaf(v, dp[cc], pdA);
                if (cc & 1) {
                    __half2 t = __floats2half2_rn(so[cc - 1], v);
                    pk[cc >> 1] = *(uint32_t*)&t;
                }
            }
#pragma unroll
            for (int cc = 64; cc < 128; cc++) {
                float v = so[cc];
                psB = fmaf(v, sp[cc], psB);
                pdB = fmaf(v, dp[cc], pdB);
                if (cc & 1) {
                    __half2 t = __floats2half2_rn(so[cc - 1], v);
                    pk[cc >> 1] = *(uint32_t*)&t;
                }
            }
            uint4* hp = (uint4*)&g_h16[(size_t)row * FDIM + half * 128];
#pragma unroll
            for (int q = 0; q < 16; q++)
                hp[q] = make_uint4(pk[4 * q], pk[4 * q + 1], pk[4 * q + 2], pk[4 * q + 3]);
            *(float2*)&g_asrc[row * 4 + half * 2] = make_float2(psA, psB);
            *(float2*)&g_adst[row * 4 + half * 2] = make_float2(pdA, pdB);
        }
    }
}

// ---------------------------------------------------------------------------
// agg: warp per dst node. Pass A: exp numerators (stored) + denom reduce.
// Pass B: alpha-weighted fp16 gather. No max pass (logits small).
// ---------------------------------------------------------------------------
__global__ void agg_kernel(float* __restrict__ out, const float* __restrict__ bias, int N) {
    int d = (blockIdx.x * blockDim.x + threadIdx.x) >> 5;
    int lane = threadIdx.x & 31;
    if (d >= N) return;
    int row = g_rowstart[d];
    int re  = g_rowstart[d + 1];
    float4 ad = *(const float4*)&g_adst[d * 4];

    // Pass A: numerators + denominator
    float4 sm = make_float4(0.f, 0.f, 0.f, 0.f);
    for (int i = row + lane; i < re; i += 32) {
        int s = g_esrc[i];
        float4 as = *(const float4*)&g_asrc[s * 4];
        float4 nu;
        nu.x = __expf(lrelu(as.x + ad.x));
        nu.y = __expf(lrelu(as.y + ad.y));
        nu.z = __expf(lrelu(as.z + ad.z));
        nu.w = __expf(lrelu(as.w + ad.w));
        *(float4*)&g_anum[(size_t)i * 4] = nu;
        sm.x += nu.x; sm.y += nu.y; sm.z += nu.z; sm.w += nu.w;
    }
#pragma unroll
    for (int sh = 16; sh; sh >>= 1) {
        sm.x += __shfl_xor_sync(0xFFFFFFFF, sm.x, sh);
        sm.y += __shfl_xor_sync(0xFFFFFFFF, sm.y, sh);
        sm.z += __shfl_xor_sync(0xFFFFFFFF, sm.z, sh);
        sm.w += __shfl_xor_sync(0xFFFFFFFF, sm.w, sh);
    }
    float rs4[4] = {1.f / sm.x, 1.f / sm.y, 1.f / sm.z, 1.f / sm.w};
    int head = lane >> 3;           // lane covers cols [lane*8, lane*8+8) -> one head
    float rs = rs4[head];

    // Pass B: weighted fp16 gather
    float acc[8] = {0.f, 0.f, 0.f, 0.f, 0.f, 0.f, 0.f, 0.f};
    for (int i = row; i < re; i++) {
        int s = g_esrc[i];                                   // broadcast
        float4 nu = *(const float4*)&g_anum[(size_t)i * 4];  // broadcast
        float al = ((const float*)&nu)[head] * rs;
        uint4 hv = *(const uint4*)&g_h16[(size_t)s * FDIM + lane * 8];
        const __half2* h2 = (const __half2*)&hv;
#pragma unroll
        for (int q = 0; q < 4; q++) {
            float2 f = __half22float2(h2[q]);
            acc[2 * q]     = fmaf(al, f.x, acc[2 * q]);
            acc[2 * q + 1] = fmaf(al, f.y, acc[2 * q + 1]);
        }
    }
    const float* bp = bias + lane * 8;
    float4 o0 = make_float4(acc[0] + bp[0], acc[1] + bp[1], acc[2] + bp[2], acc[3] + bp[3]);
    float4 o1 = make_float4(acc[4] + bp[4], acc[5] + bp[5], acc[6] + bp[6], acc[7] + bp[7]);
    float4* op = (float4*)(out + (size_t)d * FDIM + lane * 8);
    op[0] = o0;
    op[1] = o1;
}

// ---------------------------------------------------------------------------
extern "C" void kernel_launch(void* const* d_in, const int* in_sizes, int n_in,
                              void* d_out, int out_size) {
    const float* x        = (const float*)d_in[0];
    const void*  ei       = d_in[1];
    const float* W        = (const float*)d_in[2];
    const float* att_src  = (const float*)d_in[3];
    const float* att_dst  = (const float*)d_in[4];
    const float* bias     = (const float*)d_in[5];
    float* out = (float*)d_out;

    int N = in_sizes[0] / FDIM;
    int E = in_sizes[1] / 2;
    int ET = E + N;
    int nblks = (N + SCAN_B - 1) / SCAN_B;

    static int smem_set = 0;
    if (!smem_set) {
        cudaFuncSetAttribute(gemm_tc_kernel, cudaFuncAttributeMaxDynamicSharedMemorySize, GEMM_SMEM);
        smem_set = 1;
    }

    detect_kernel<<<1, 256>>>((const unsigned int*)ei, in_sizes[1]);
    zero_kernel<<<(N + 255) / 256, 256>>>(N);
    hist_kernel<<<(ET + 255) / 256, 256>>>(ei, E, N);
    scan1_kernel<<<nblks, SCAN_B>>>(N);
    scan2_kernel<<<1, 32>>>(nblks);
    scan3_kernel<<<nblks, SCAN_B>>>(N);
    fill_kernel<<<(ET + 255) / 256, 256>>>(ei, E, N);

    gemm_tc_kernel<<<(N + BM - 1) / BM, 256, GEMM_SMEM>>>(x, W, att_src, att_dst, N);

    agg_kernel<<<((size_t)N * 32 + 255) / 256, 256>>>(out, bias, N);
}